// round 12
// baseline (speedup 1.0000x reference)
#include <cuda_runtime.h>
#include <cstdint>

// ---------------------------------------------------------------------------
// Problem constants
//   B=32, T=2048, C=256, H=256, STRIDE=2, TC=1024, NC1=100, NC2=90
// ---------------------------------------------------------------------------
#define TCON 1024
typedef unsigned long long u64;

// ---- cluster-LSTM smem layout (floats) ----
// sw  : 4 gates x 32 j x 260 (pad)   = 33280
// shh : 2 bufs x 4 b x 260 (pad)     = 2080
// sgp : 4 gates x 32 j x 5 (pad)     = 640
// snew: 4 b x 32 j                   = 128
#define L2_SW_FLOATS 33280
#define L2_SHH_OFF   33280
#define L2_SHH_FLOATS 2080
#define L2_SG_OFF    35360
#define L2_SN_OFF    36000
#define L2_TOT_FLOATS 36128
#define L2_SMEM (L2_TOT_FLOATS * 4)     // 144512 bytes

// ---------------------------------------------------------------------------
// Scratch (device globals; no runtime allocation allowed)
// ---------------------------------------------------------------------------
__device__ float g_y[32768 * 256];
__device__ float g_pre_f[33554432];     // 32768*1024
__device__ float g_pre_r[33554432];
__device__ float g_h0[16777216];        // 32768*512
__device__ float g_h1[16777216];
__device__ float g_fc_part[32 * 192 * 32];

// ---------------------------------------------------------------------------
// Helpers
// ---------------------------------------------------------------------------
__device__ __forceinline__ void fma2(u64& acc, u64 a, u64 b) {
    asm("fma.rn.f32x2 %0, %1, %2, %0;" : "+l"(acc) : "l"(a), "l"(b));
}
__device__ __forceinline__ float2 u2f2(u64 v) {
    float2 r;
    asm("mov.b64 {%0,%1}, %2;" : "=f"(r.x), "=f"(r.y) : "l"(v));
    return r;
}
__device__ __forceinline__ u64 dup2(float a) {
    u64 r;
    asm("mov.b64 %0, {%1,%1};" : "=l"(r) : "f"(a));
    return r;
}
__device__ __forceinline__ float sigf(float x) {
    return __fdividef(1.f, 1.f + __expf(-x));
}
__device__ __forceinline__ float tanh_fast(float x) {
    return 2.f * sigf(2.f * x) - 1.f;
}
__device__ __forceinline__ uint32_t smem_u32(const void* p) {
    uint32_t a;
    asm("{ .reg .u64 t; cvta.to.shared.u64 t, %1; cvt.u32.u64 %0, t; }"
        : "=r"(a) : "l"(p));
    return a;
}

// ---------------------------------------------------------------------------
// Conv1d(k=3, stride=2, pad=1) + BN(affine, eval) + ReLU
// ---------------------------------------------------------------------------
__global__ void conv_bn(const float* __restrict__ x,
                        const float* __restrict__ cw,
                        const float* __restrict__ cb,
                        const float* __restrict__ gmm,
                        const float* __restrict__ bet,
                        const float* __restrict__ mean,
                        const float* __restrict__ var) {
    int tb = blockIdx.x;
    int t = tb >> 5, b = tb & 31;
    int c = threadIdx.x;
    float w0 = cw[c * 3 + 0], w1 = cw[c * 3 + 1], w2 = cw[c * 3 + 2];
    const float* xb = x + b * 2048;
    int xi = t * 2;
    float xm1 = (xi >= 1) ? xb[xi - 1] : 0.f;
    float x0 = xb[xi];
    float xp1 = xb[xi + 1];
    float conv = fmaf(xm1, w0, fmaf(x0, w1, xp1 * w2)) + cb[c];
    float inv = gmm[c] * rsqrtf(var[c] + 1e-5f);
    float v = conv * inv + (bet[c] - mean[c] * inv);
    g_y[(size_t)tb * 256 + c] = fmaxf(v, 0.f);
}

// ---------------------------------------------------------------------------
// SGEMM (TN): C[M=32768][N=1024] = A[M][K] * B[N][K]^T + bias[N]
// 128x128 block tile, BK=8, 256 threads, 8x8 micro-tile, f32x2-packed FMAs.
// ---------------------------------------------------------------------------
__global__ void __launch_bounds__(256) sgemm_tn(const float* __restrict__ A,
                                                const float* __restrict__ B,
                                                const float* __restrict__ bias,
                                                float* __restrict__ C,
                                                int K) {
    __shared__ __align__(16) float As[8][132];
    __shared__ __align__(16) float Bs[8][132];
    int bm = blockIdx.y * 128;
    int bn = blockIdx.x * 128;
    int tid = threadIdx.x;
    int tx = tid & 15, ty = tid >> 4;
    int lrow = tid >> 1;
    int lk = (tid & 1) * 4;
    const float* Ap = A + (size_t)(bm + lrow) * K + lk;
    const float* Bp = B + (size_t)(bn + lrow) * K + lk;

    u64 acc2[8][4];
#pragma unroll
    for (int i = 0; i < 8; i++)
#pragma unroll
        for (int j = 0; j < 4; j++) acc2[i][j] = 0ull;

    for (int k0 = 0; k0 < K; k0 += 8) {
        float4 av = *(const float4*)(Ap + k0);
        float4 bv = *(const float4*)(Bp + k0);
        __syncthreads();
        As[lk + 0][lrow] = av.x; As[lk + 1][lrow] = av.y;
        As[lk + 2][lrow] = av.z; As[lk + 3][lrow] = av.w;
        Bs[lk + 0][lrow] = bv.x; Bs[lk + 1][lrow] = bv.y;
        Bs[lk + 2][lrow] = bv.z; Bs[lk + 3][lrow] = bv.w;
        __syncthreads();
#pragma unroll
        for (int kk = 0; kk < 8; kk++) {
            float a[8];
            *(float4*)&a[0] = *(const float4*)&As[kk][ty * 8];
            *(float4*)&a[4] = *(const float4*)&As[kk][ty * 8 + 4];
            ulonglong2 bl = *(const ulonglong2*)&Bs[kk][tx * 8];
            ulonglong2 bh = *(const ulonglong2*)&Bs[kk][tx * 8 + 4];
            u64 b2[4] = {bl.x, bl.y, bh.x, bh.y};
#pragma unroll
            for (int i = 0; i < 8; i++) {
                u64 a2 = dup2(a[i]);
#pragma unroll
                for (int j2 = 0; j2 < 4; j2++) fma2(acc2[i][j2], a2, b2[j2]);
            }
        }
    }
#pragma unroll
    for (int i = 0; i < 8; i++) {
        size_t m = (size_t)(bm + ty * 8 + i);
        int n = bn + tx * 8;
        float2 p0 = u2f2(acc2[i][0]);
        float2 p1 = u2f2(acc2[i][1]);
        float2 p2 = u2f2(acc2[i][2]);
        float2 p3 = u2f2(acc2[i][3]);
        float4 o0, o1;
        o0.x = p0.x + bias[n + 0]; o0.y = p0.y + bias[n + 1];
        o0.z = p1.x + bias[n + 2]; o0.w = p1.y + bias[n + 3];
        o1.x = p2.x + bias[n + 4]; o1.y = p2.y + bias[n + 5];
        o1.z = p3.x + bias[n + 6]; o1.w = p3.y + bias[n + 7];
        *(float4*)&C[m * 1024 + n] = o0;
        *(float4*)&C[m * 1024 + n + 4] = o1;
    }
}

// ---------------------------------------------------------------------------
// BiLSTM recurrence, cluster version. Grid = 128 CTAs, cluster (8,1,1).
// Cluster id c = blockIdx.x>>3: dir = c>>3, batch-group bg = c&7 (4 batches).
// CTA rank cr in [0,8): owns j-slice [cr*32, cr*32+32) with all 4 gates
// (weights 130KB in SMEM) and all 256 h values for the cluster's 4 batches
// (double-buffered). Per-step sync = DSMEM h broadcast + cluster barrier.
// No global synchronization at all (batches are independent across clusters).
//
// Thread roles (256 threads):
//   GEMV:   b4 = tid&3, js = (tid>>2)&7, warp w = tid>>5: g = w&3, jh = w>>2
//           thread computes gate dots for j = jh*8+js and j+16, batch b4.
//   combine (tid<128): cj = tid&31 (j), cb = tid>>5 (batch) — activations,
//           c-state, h, DSMEM broadcast to all 8 CTAs.
//   w==7:   coalesced STG of the CTA's 128 h values to hout.
// ---------------------------------------------------------------------------
__global__ void __launch_bounds__(256, 1) __cluster_dims__(8, 1, 1)
lstm_cluster(const float* __restrict__ pre_fw,
             const float* __restrict__ pre_rv,
             const float* __restrict__ whh_fw,
             const float* __restrict__ whh_rv,
             float* __restrict__ hout) {
    extern __shared__ float smem[];
    float* sw   = smem;                 // [g*32+jl][260]
    float* shh  = smem + L2_SHH_OFF;    // [buf][b][260]
    float* sgp  = smem + L2_SG_OFF;     // [(g*32+jl)*5 + b]
    float* snew = smem + L2_SN_OFF;     // [b*32 + jl]

    const int tid = threadIdx.x;
    const int cid = blockIdx.x >> 3;
    const int dir = cid >> 3;
    const int bg  = cid & 7;
    uint32_t cr;
    asm("mov.u32 %0, %%cluster_ctarank;" : "=r"(cr));

    const float* whh = dir ? whh_rv : whh_fw;
    const float* pre = dir ? pre_rv : pre_fw;
    const int foff = dir ? 256 : 0;

    // Load W_hh slice: sw[(g*32+jl)*260 + k] = whh[(g*256 + cr*32 + jl)*256 + k]
    for (int i = tid; i < 32768; i += 256) {
        int row = i >> 8;               // g*32 + jl
        int k = i & 255;
        int g = row >> 5, jl = row & 31;
        sw[row * 260 + k] = whh[((size_t)(g * 256 + (int)cr * 32 + jl)) * 256 + k];
    }
    for (int i = tid; i < L2_SHH_FLOATS; i += 256) shh[i] = 0.f;
    __syncthreads();
    // All CTAs' h buffers zeroed before any peer may write into them.
    asm volatile("barrier.cluster.arrive.aligned;" ::: "memory");
    asm volatile("barrier.cluster.wait.aligned;" ::: "memory");

    // thread roles
    const int b4 = tid & 3;
    const int js = (tid >> 2) & 7;
    const int w  = tid >> 5;
    const int g  = w & 3;
    const int jh = w >> 2;
    const int jl0 = jh * 8 + js;        // 0..15 (second j = jl0+16)
    const int cj = tid & 31;            // combine: j
    const int cb = tid >> 5;            // combine: batch (valid for tid<128)

    const float* w0p = sw + (g * 32 + jl0) * 260;
    const float* w1p = w0p + 16 * 260;
    const uint32_t smem_base = smem_u32(smem);

    float c_state = 0.f;
    int t = dir ? (TCON - 1) : 0;
    float p_i = 0.f, p_f = 0.f, p_g = 0.f, p_o = 0.f;
    if (tid < 128) {
        const float* pr = pre + ((size_t)t * 32 + bg * 4 + cb) * 1024 + cr * 32 + cj;
        p_i = pr[0]; p_f = pr[256]; p_g = pr[512]; p_o = pr[768];
    }

    int buf = 0;
    for (int step = 0; step < TCON; step++) {
        // ---- GEMV: two gate dots (j, j+16) for batch b4 ----
        const float* hb = shh + buf * 1040 + b4 * 260;
        u64 a0 = 0ull, a1 = 0ull;
#pragma unroll 4
        for (int k4 = 0; k4 < 64; k4++) {
            ulonglong2 hv  = *(const ulonglong2*)(hb  + k4 * 4);
            ulonglong2 wv0 = *(const ulonglong2*)(w0p + k4 * 4);
            ulonglong2 wv1 = *(const ulonglong2*)(w1p + k4 * 4);
            fma2(a0, wv0.x, hv.x); fma2(a0, wv0.y, hv.y);
            fma2(a1, wv1.x, hv.x); fma2(a1, wv1.y, hv.y);
        }
        float2 s0 = u2f2(a0), s1 = u2f2(a1);
        sgp[(g * 32 + jl0) * 5 + b4] = s0.x + s0.y;
        sgp[(g * 32 + jl0 + 16) * 5 + b4] = s1.x + s1.y;
        __syncthreads();

        int t_next = dir ? (t - 1) : (t + 1);

        // ---- combine: activations + c-state + DSMEM broadcast ----
        if (tid < 128) {
            float gi = sgp[(0 * 32 + cj) * 5 + cb] + p_i;
            float gf = sgp[(1 * 32 + cj) * 5 + cb] + p_f;
            float gg = sgp[(2 * 32 + cj) * 5 + cb] + p_g;
            float go = sgp[(3 * 32 + cj) * 5 + cb] + p_o;
            float iv = sigf(gi), fv = sigf(gf), zv = tanh_fast(gg), ov = sigf(go);
            c_state = fv * c_state + iv * zv;
            float h_val = ov * tanh_fast(c_state);
            snew[cb * 32 + cj] = h_val;

            // broadcast h into every CTA's next-buffer h slot
            uint32_t lbase = smem_base +
                (uint32_t)((L2_SHH_OFF + (buf ^ 1) * 1040 + cb * 260 + (int)cr * 32 + cj) * 4);
#pragma unroll
            for (int p = 0; p < 8; p++) {
                uint32_t raddr;
                asm("mapa.shared::cluster.u32 %0, %1, %2;" : "=r"(raddr) : "r"(lbase), "r"(p));
                asm volatile("st.shared::cluster.f32 [%0], %1;" :: "r"(raddr), "f"(h_val) : "memory");
            }

            if (step != TCON - 1) {
                const float* prn = pre + ((size_t)t_next * 32 + bg * 4 + cb) * 1024 + cr * 32 + cj;
                p_i = prn[0]; p_f = prn[256]; p_g = prn[512]; p_o = prn[768];
            }
        }
        __syncthreads();

        // ---- coalesced global store of this CTA's h (warp 7) ----
        if (w == 7) {
            int lb = (tid & 31) >> 3;   // 0..3
            int q = tid & 7;            // 0..7
            float4 hv4 = *(const float4*)(snew + lb * 32 + q * 4);
            *(float4*)&hout[((size_t)t * 32 + bg * 4 + lb) * 512 + foff + (int)cr * 32 + q * 4] = hv4;
        }

        // ---- cluster barrier: release our DSMEM writes, acquire peers' ----
        asm volatile("barrier.cluster.arrive.aligned;" ::: "memory");
        asm volatile("barrier.cluster.wait.aligned;" ::: "memory");
        buf ^= 1;
        t = t_next;
    }
}

// ---------------------------------------------------------------------------
// FC heads (split-k partials + deterministic reduce)
// ---------------------------------------------------------------------------
__global__ void __launch_bounds__(256) fc_main(const float* __restrict__ h,
                                               const float* __restrict__ w1,
                                               const float* __restrict__ w2) {
    extern __shared__ float sh[];
    int kc = blockIdx.x;
    int grp = blockIdx.y;
    int tid = threadIdx.x;
    int nl = tid >> 4, bb = tid & 15;
    int n = grp * 16 + nl;
    bool valid = (n < 190);
    const float* wrow = valid
        ? (n < 100 ? w1 + (size_t)n * 524288 : w2 + (size_t)(n - 100) * 524288)
        : w1;

    float ax = 0.f, ay = 0.f;
    for (int tt = 0; tt < 32; tt++) {
        int t = kc * 32 + tt;
        const float* slab = h + (size_t)t * 16384;
        __syncthreads();
        for (int i = tid; i < 4096; i += 256) {
            int b = i >> 7;
            int q = i & 127;
            float4 v = *(const float4*)&slab[b * 512 + q * 4];
            int bl = (b & 15) * 2 + (b >> 4);
            int f = q * 4;
            sh[(f + 0) * 32 + bl] = v.x;
            sh[(f + 1) * 32 + bl] = v.y;
            sh[(f + 2) * 32 + bl] = v.z;
            sh[(f + 3) * 32 + bl] = v.w;
        }
        __syncthreads();
        const float* wp = wrow + (size_t)t * 512;
#pragma unroll 4
        for (int f4 = 0; f4 < 128; f4++) {
            float4 wv = *(const float4*)(wp + f4 * 4);
            const float* s0 = sh + (f4 * 4) * 32 + bb * 2;
            float2 a0 = *(const float2*)(s0);
            float2 a1 = *(const float2*)(s0 + 32);
            float2 a2 = *(const float2*)(s0 + 64);
            float2 a3 = *(const float2*)(s0 + 96);
            ax = fmaf(wv.x, a0.x, ax); ay = fmaf(wv.x, a0.y, ay);
            ax = fmaf(wv.y, a1.x, ax); ay = fmaf(wv.y, a1.y, ay);
            ax = fmaf(wv.z, a2.x, ax); ay = fmaf(wv.z, a2.y, ay);
            ax = fmaf(wv.w, a3.x, ax); ay = fmaf(wv.w, a3.y, ay);
        }
    }
    if (valid) {
        g_fc_part[((size_t)kc * 192 + n) * 32 + bb] = ax;
        g_fc_part[((size_t)kc * 192 + n) * 32 + bb + 16] = ay;
    }
}

__global__ void fc_reduce(const float* __restrict__ b1,
                          const float* __restrict__ b2,
                          float* __restrict__ out) {
    int i = blockIdx.x * 256 + threadIdx.x;
    if (i >= 6080) return;
    int n = i >> 5;
    int b = i & 31;
    float s = (n < 100) ? b1[n] : b2[n - 100];
#pragma unroll
    for (int kc = 0; kc < 32; kc++)
        s += g_fc_part[((size_t)kc * 192 + n) * 32 + b];
    if (n < 100) out[b * 100 + n] = s;
    else out[3200 + b * 90 + (n - 100)] = s;
}

// ---------------------------------------------------------------------------
// Launch
// ---------------------------------------------------------------------------
extern "C" void kernel_launch(void* const* d_in, const int* in_sizes, int n_in,
                              void* d_out, int out_size) {
    const float* x       = (const float*)d_in[0];
    const float* conv_w  = (const float*)d_in[1];
    const float* conv_b  = (const float*)d_in[2];
    const float* bn_g    = (const float*)d_in[3];
    const float* bn_b    = (const float*)d_in[4];
    const float* bn_m    = (const float*)d_in[5];
    const float* bn_v    = (const float*)d_in[6];
    const float* w_ih_f0 = (const float*)d_in[7];
    const float* w_hh_f0 = (const float*)d_in[8];
    const float* b_f0    = (const float*)d_in[9];
    const float* w_ih_r0 = (const float*)d_in[10];
    const float* w_hh_r0 = (const float*)d_in[11];
    const float* b_r0    = (const float*)d_in[12];
    const float* w_ih_f1 = (const float*)d_in[13];
    const float* w_hh_f1 = (const float*)d_in[14];
    const float* b_f1    = (const float*)d_in[15];
    const float* w_ih_r1 = (const float*)d_in[16];
    const float* w_hh_r1 = (const float*)d_in[17];
    const float* b_r1    = (const float*)d_in[18];
    const float* fc1_w   = (const float*)d_in[19];
    const float* fc1_b   = (const float*)d_in[20];
    const float* fc2_w   = (const float*)d_in[21];
    const float* fc2_b   = (const float*)d_in[22];
    float* out = (float*)d_out;

    float *py, *ppf, *ppr, *ph0, *ph1;
    cudaGetSymbolAddress((void**)&py, g_y);
    cudaGetSymbolAddress((void**)&ppf, g_pre_f);
    cudaGetSymbolAddress((void**)&ppr, g_pre_r);
    cudaGetSymbolAddress((void**)&ph0, g_h0);
    cudaGetSymbolAddress((void**)&ph1, g_h1);

    cudaFuncSetAttribute(lstm_cluster, cudaFuncAttributeMaxDynamicSharedMemorySize, L2_SMEM);
    cudaFuncSetAttribute(fc_main, cudaFuncAttributeMaxDynamicSharedMemorySize, 65536);

    // 1) conv + bn + relu
    conv_bn<<<32768, 256>>>(x, conv_w, conv_b, bn_g, bn_b, bn_m, bn_v);

    // 2) layer 0 input projections (K=256)
    dim3 gg(8, 256);
    sgemm_tn<<<gg, 256>>>(py, w_ih_f0, b_f0, ppf, 256);
    sgemm_tn<<<gg, 256>>>(py, w_ih_r0, b_r0, ppr, 256);

    // 3) layer 0 recurrence (cluster kernel)
    lstm_cluster<<<128, 256, L2_SMEM>>>(ppf, ppr, w_hh_f0, w_hh_r0, ph0);

    // 4) layer 1 input projections (K=512)
    sgemm_tn<<<gg, 256>>>(ph0, w_ih_f1, b_f1, ppf, 512);
    sgemm_tn<<<gg, 256>>>(ph0, w_ih_r1, b_r1, ppr, 512);

    // 5) layer 1 recurrence
    lstm_cluster<<<128, 256, L2_SMEM>>>(ppf, ppr, w_hh_f1, w_hh_r1, ph1);

    // 6) FC heads
    dim3 fg(32, 12);
    fc_main<<<fg, 256, 65536>>>(ph1, fc1_w, fc2_w);
    fc_reduce<<<24, 256>>>(fc1_b, fc2_b, out);
}